// round 9
// baseline (speedup 1.0000x reference)
#include <cuda_runtime.h>
#include <cuda_bf16.h>
#include <cstdint>

#define NB 16384
#define N1 1024
#define K1 512
#define N2 512
#define K2 1024
// row partition: ffma rows [0, MF), mma rows [MF, NB)
#define MF 11776          // 92 tiles of 128
#define MR 4608           // 36 tiles of 128
#define F0MG 736          // MF/16
#define NCTA 304
#define NFFMA 152         // CTAs 0..151 ffma, 152..303 mma

// ---------------- device-global scratch ------------------------------------
__device__ float    g_W1p[N1 * K1], g_W2p[N2 * K2];
__device__ float    g_h[(size_t)MF * N1];
__device__ uint32_t g_zf1[(size_t)NB * K1 / 2], g_zf2[(size_t)NB * K1 / 2];
__device__ uint32_t g_hf1[(size_t)NB * N1 / 2], g_hf2[(size_t)NB * N1 / 2];
__device__ uint32_t g_w1f1[N1 * K1 / 2], g_w1f2[N1 * K1 / 2];
__device__ uint32_t g_w2f1[N2 * K2 / 2], g_w2f2[N2 * K2 / 2];
__device__ float g_beff1[N1], g_beff2[N2], g_c[N1];
__device__ float g_trp[8][NB];
__device__ int g_qf, g_qm;

// ---------------- helpers --------------------------------------------------
__device__ __forceinline__ uint32_t smem_u32(const void* p) {
    uint32_t a;
    asm("{ .reg .u64 t; cvta.to.shared.u64 t, %1; cvt.u32.u64 %0, t; }" : "=r"(a) : "l"(p));
    return a;
}
#define CP16(dst, src) \
    asm volatile("cp.async.cg.shared.global [%0], [%1], 16;" \
        :: "r"(dst), "l"(__cvta_generic_to_global(src)))
#define CP_COMMIT() asm volatile("cp.async.commit_group;")
#define CP_WAIT1()  asm volatile("cp.async.wait_group 1;")
#define CP_WAIT0()  asm volatile("cp.async.wait_group 0;")
#define LDS128(r, addr) \
    asm volatile("ld.shared.v4.b32 {%0,%1,%2,%3}, [%4];" \
        : "=r"((r)[0]), "=r"((r)[1]), "=r"((r)[2]), "=r"((r)[3]) : "r"(addr))

__device__ __forceinline__ void mma_bf16(float* d, const uint32_t* a, const uint32_t* b) {
    asm volatile(
        "mma.sync.aligned.m16n8k16.row.col.f32.bf16.bf16.f32 "
        "{%0,%1,%2,%3}, {%4,%5,%6,%7}, {%8,%9}, {%0,%1,%2,%3};"
        : "+f"(d[0]), "+f"(d[1]), "+f"(d[2]), "+f"(d[3])
        : "r"(a[0]), "r"(a[1]), "r"(a[2]), "r"(a[3]), "r"(b[0]), "r"(b[1]));
}

__device__ __forceinline__ void split2(float v0, float v1, uint32_t& w1, uint32_t& w2) {
    __nv_bfloat16 h0 = __float2bfloat16_rn(v0);
    __nv_bfloat16 h1 = __float2bfloat16_rn(v1);
    float r0 = v0 - __bfloat162float(h0);
    float r1 = v1 - __bfloat162float(h1);
    __nv_bfloat16 l0 = __float2bfloat16_rn(r0);
    __nv_bfloat16 l1 = __float2bfloat16_rn(r1);
    w1 = ((uint32_t)__bfloat16_as_ushort(h1) << 16) | __bfloat16_as_ushort(h0);
    w2 = ((uint32_t)__bfloat16_as_ushort(l1) << 16) | __bfloat16_as_ushort(l0);
}

__device__ __noinline__ bool exact_mask(const float* __restrict__ z,
                                        const float* __restrict__ W1,
                                        int row, int col) {
    const float* zr = z + (size_t)row * K1;
    const float* wr = W1 + (size_t)col * (K1 + 1);
    double s0 = 0, s1 = 0, s2 = 0, s3 = 0;
    for (int d = 0; d < K1; d += 4) {
        s0 += (double)zr[d + 0] * (double)wr[d + 0];
        s1 += (double)zr[d + 1] * (double)wr[d + 1];
        s2 += (double)zr[d + 2] * (double)wr[d + 2];
        s3 += (double)zr[d + 3] * (double)wr[d + 3];
    }
    double s = ((s0 + s1) + (s2 + s3)) + (double)g_beff1[col];
    return s > 0.0;
}

// ---------------- prep kernels ---------------------------------------------
__global__ void prep_pack(const float* __restrict__ W1, const float* __restrict__ W2) {
    int idx = blockIdx.x * 256 + threadIdx.x;
    if (idx < N1 * K1) {
        int n = idx >> 9, k = idx & 511;
        g_W1p[idx] = W1[n * 513 + k];
    } else {
        int j = idx - N1 * K1;
        if (j < N2 * K2) {
            int n = j >> 10, k = j & 1023;
            g_W2p[j] = W2[n * 1025 + k];
        }
    }
}

__global__ void prep_w(const float* __restrict__ W1, const float* __restrict__ W2) {
    int p = blockIdx.x * 256 + threadIdx.x;
    if (p < N1 * K1 / 2) {
        int n = p >> 8, q = p & 255;
        uint32_t w1, w2;
        split2(W1[n * 513 + 2 * q], W1[n * 513 + 2 * q + 1], w1, w2);
        int s = q >> 3, t = ((n & 7) << 2) | (q & 3), g = n >> 3, j = (q >> 2) & 1;
        int off = ((s * 32 + t) * (N1 / 8) + g) * 2 + j;
        g_w1f1[off] = w1; g_w1f2[off] = w2;
    } else {
        int p2 = p - N1 * K1 / 2;
        if (p2 < N2 * K2 / 2) {
            int n = p2 >> 9, q = p2 & 511;
            uint32_t w1, w2;
            split2(W2[n * 1025 + 2 * q], W2[n * 1025 + 2 * q + 1], w1, w2);
            int s = q >> 3, t = ((n & 7) << 2) | (q & 3), g = n >> 3, j = (q >> 2) & 1;
            int off = ((s * 32 + t) * (N2 / 8) + g) * 2 + j;
            g_w2f1[off] = w1; g_w2f2[off] = w2;
        }
    }
}

__global__ void prep_zf(const float* __restrict__ z) {   // mma rows only
    int i4 = MF * (K1 / 4) + blockIdx.x * 256 + threadIdx.x;
    int m = i4 >> 7, qq = (i4 & 127) * 2;
    float4 v = ((const float4*)z)[i4];
    int f = m >> 4;
    #pragma unroll
    for (int pi = 0; pi < 2; pi++) {
        int q = qq + pi;
        float a0 = pi ? v.z : v.x;
        float a1 = pi ? v.w : v.y;
        uint32_t w1, w2;
        split2(a0, a1, w1, w2);
        int s = q >> 3, t = ((m & 7) << 2) | (q & 3);
        int jr = ((m >> 3) & 1) | (((q >> 2) & 1) << 1);
        int off = ((f * (K1 / 16) + s) * 32 + t) * 4 + jr;
        g_zf1[off] = w1; g_zf2[off] = w2;
    }
}

// fast c/bias: W1 AND W2 both smem-tiled (coalesced global traffic only)
__global__ void prep_cbias(const float* __restrict__ t,
                           const float* __restrict__ W1, const float* __restrict__ b1,
                           const float* __restrict__ W2, const float* __restrict__ b2) {
    __shared__ float w2s[32][129];
    __shared__ float w1s[128][33];
    int tid = threadIdx.x;                    // 128 threads
    int j = blockIdx.x * 128 + tid;
    float t0 = t[0];
    float acc = 0.f;
    for (int k0 = 0; k0 < K1; k0 += 32) {
        #pragma unroll
        for (int i = 0; i < 32; i++) {        // W2 tile [32 k][128 j]
            int idx = tid + i * 128;
            int kk = idx >> 7, jj = idx & 127;
            w2s[kk][jj] = W2[(size_t)(k0 + kk) * 1025 + blockIdx.x * 128 + jj];
        }
        #pragma unroll
        for (int i = 0; i < 32; i++) {        // W1 tile [128 j][32 k]
            int idx = tid + i * 128;
            int jr = idx >> 5, kk = idx & 31;
            w1s[jr][kk] = W1[(size_t)(blockIdx.x * 128 + jr) * 513 + k0 + kk];
        }
        __syncthreads();
        #pragma unroll 8
        for (int kk = 0; kk < 32; kk++)
            acc += w2s[kk][tid] * w1s[tid][kk];
        __syncthreads();
    }
    g_c[j] = acc;
    g_beff1[j] = b1[j] + t0 * W1[(size_t)j * 513 + 512];
    if (j < N2) g_beff2[j] = b2[j] + t0 * W2[(size_t)j * 1025 + 1024];
}

__global__ void zero_q() { g_qf = 0; g_qm = 0; }

__global__ void trace_combine(float* __restrict__ out) {   // mma rows only
    int i = MF + blockIdx.x * 256 + threadIdx.x;
    float s = 0.f;
    #pragma unroll
    for (int b = 0; b < 8; b++) s += g_trp[b][i];
    out[(size_t)NB * N2 + i] = -s;
}

// ---------------- smem layout (mma stages) ---------------------------------
static constexpr int ST_A2 = 8192;
static constexpr int ST_B1 = 16384;
static constexpr int ST_B2 = 25600;
static constexpr int ST_SZ = 34816;
static constexpr int SMEM_BYTES = 3 * ST_SZ;   // 104448, ffma uses first 8KB
static constexpr float TAU = 1e-3f;

// ---------------- ffma tile (R1 body, queue-driven) -------------------------
template<int PHASE>
__device__ __forceinline__ void ffma_tile(char* smem, float* outX,
                                          const float* __restrict__ zin,
                                          int xt, int yt, int tid) {
    constexpr int K   = (PHASE == 1) ? K1 : K2;
    constexpr int LDC = (PHASE == 1) ? N1 : N2;
    const float* A  = (PHASE == 1) ? zin : (const float*)g_h;
    const float* Bw = (PHASE == 1) ? (const float*)g_W1p : (const float*)g_W2p;
    float* outp     = (PHASE == 1) ? (float*)g_h : outX;

    float* As = (float*)smem;
    float* Bs = (float*)(smem + 4096);

    const int m0 = yt * 128;
    const int n0 = xt * 128;
    const int lrow = tid >> 1;
    const int lk4  = (tid & 1) << 2;
    const float* Ap = A  + (size_t)(m0 + lrow) * K + lk4;
    const float* Bp = Bw + (size_t)(n0 + lrow) * K + lk4;
    const int tx = tid & 15;
    const int ty = tid >> 4;

    float acc[8][8];
    #pragma unroll
    for (int i = 0; i < 8; i++)
        #pragma unroll
        for (int j = 0; j < 8; j++) acc[i][j] = 0.f;

    float tr = 0.f;
    const bool do_trace = (PHASE == 2) && (xt == 0);

    float4 av = *(const float4*)Ap;
    float4 bv = *(const float4*)Bp;

    for (int k0 = 0; k0 < K; k0 += 8) {
        As[(lk4 + 0) * 128 + lrow] = av.x;
        As[(lk4 + 1) * 128 + lrow] = av.y;
        As[(lk4 + 2) * 128 + lrow] = av.z;
        As[(lk4 + 3) * 128 + lrow] = av.w;
        Bs[(lk4 + 0) * 128 + lrow] = bv.x;
        Bs[(lk4 + 1) * 128 + lrow] = bv.y;
        Bs[(lk4 + 2) * 128 + lrow] = bv.z;
        Bs[(lk4 + 3) * 128 + lrow] = bv.w;

        if (do_trace) {
            const float4 cv = *(const float4*)(g_c + k0 + lk4);
            tr += (av.x > 0.f) ? cv.x : 0.f;
            tr += (av.y > 0.f) ? cv.y : 0.f;
            tr += (av.z > 0.f) ? cv.z : 0.f;
            tr += (av.w > 0.f) ? cv.w : 0.f;
        }
        __syncthreads();
        if (k0 + 8 < K) {
            av = *(const float4*)(Ap + k0 + 8);
            bv = *(const float4*)(Bp + k0 + 8);
        }
        #pragma unroll
        for (int kk = 0; kk < 8; kk++) {
            float4 a0 = *(const float4*)&As[kk * 128 + ty * 4];
            float4 a1 = *(const float4*)&As[kk * 128 + ty * 4 + 64];
            float4 b0 = *(const float4*)&Bs[kk * 128 + tx * 4];
            float4 b1 = *(const float4*)&Bs[kk * 128 + tx * 4 + 64];
            float a[8] = {a0.x, a0.y, a0.z, a0.w, a1.x, a1.y, a1.z, a1.w};
            float b[8] = {b0.x, b0.y, b0.z, b0.w, b1.x, b1.y, b1.z, b1.w};
            #pragma unroll
            for (int i = 0; i < 8; i++)
                #pragma unroll
                for (int j = 0; j < 8; j++)
                    acc[i][j] += a[i] * b[j];
        }
        __syncthreads();
    }

    const float* bias = (PHASE == 1) ? g_beff1 : g_beff2;
    const float4 be0 = *(const float4*)(bias + n0 + tx * 4);
    const float4 be1 = *(const float4*)(bias + n0 + 64 + tx * 4);
    #pragma unroll
    for (int i = 0; i < 8; i++) {
        int m = m0 + ty * 4 + (i & 3) + ((i >= 4) ? 64 : 0);
        float v[8];
        v[0] = acc[i][0] + be0.x; v[1] = acc[i][1] + be0.y;
        v[2] = acc[i][2] + be0.z; v[3] = acc[i][3] + be0.w;
        v[4] = acc[i][4] + be1.x; v[5] = acc[i][5] + be1.y;
        v[6] = acc[i][6] + be1.z; v[7] = acc[i][7] + be1.w;
        if (PHASE == 1) {
            #pragma unroll
            for (int j = 0; j < 8; j++) v[j] = fmaxf(v[j], 0.f);
        }
        float* cp = outp + (size_t)m * LDC + n0 + tx * 4;
        *(float4*)cp        = make_float4(v[0], v[1], v[2], v[3]);
        *(float4*)(cp + 64) = make_float4(v[4], v[5], v[6], v[7]);
    }
    if (do_trace) {
        float tro = __shfl_xor_sync(0xffffffffu, tr, 1);
        if ((tid & 1) == 0)
            outp[(size_t)NB * N2 + (m0 + lrow)] = -(tr + tro);
    }
}

// ---------------- mma tile (R6 body, 128x128, queue-driven) -----------------
template<int PHASE>
__device__ __forceinline__ void mma_tile(char* smem, float* outp,
                                         const float* __restrict__ zP,
                                         const float* __restrict__ W1P,
                                         int xt, int yt, int tid) {
    constexpr int N    = (PHASE == 1) ? N1 : N2;
    constexpr int K    = (PHASE == 1) ? K1 : K2;
    constexpr int KS16 = K / 16;
    constexpr int NG   = N / 8;
    constexpr int NC   = K / 32;

    const uint32_t* A1 = (PHASE == 1) ? g_zf1  : g_hf1;
    const uint32_t* A2 = (PHASE == 1) ? g_zf2  : g_hf2;
    const uint32_t* B1 = (PHASE == 1) ? g_w1f1 : g_w2f1;
    const uint32_t* B2 = (PHASE == 1) ? g_w1f2 : g_w2f2;
    const float* bias  = (PHASE == 1) ? g_beff1 : g_beff2;

    const uint32_t sbase = smem_u32(smem);
    const int lane = tid & 31, wid = tid >> 5;
    const int wm = wid >> 2, wn = wid & 3;
    const int f0 = F0MG + yt * 8;     // absolute m0/16
    const int g0 = xt * 16;

    auto load_stage = [&](int buf, int c) {
        uint32_t st = sbase + buf * ST_SZ;
        int s0u = c * 2;
        #pragma unroll
        for (int i = 0; i < 2; i++) {
            int idx = tid + i * 256;
            int s = idx >> 8, f = (idx >> 5) & 7, tt = idx & 31;
            size_t go = (((size_t)(f0 + f) * KS16 + s0u + s) * 32 + tt) * 4;
            uint32_t so = (uint32_t)(((s * 8 + f) * 32 + tt) * 16);
            CP16(st + so,         A1 + go);
            CP16(st + ST_A2 + so, A2 + go);
        }
        #pragma unroll
        for (int i = 0; i < 2; i++) {
            int idx = tid + i * 256;
            int s = idx >> 8, tt = (idx >> 3) & 31, q = idx & 7;
            size_t go = (((size_t)(s0u + s) * 32 + tt) * NG + g0 + 2 * q) * 2;
            uint32_t so = (uint32_t)((s * 32 + tt) * 144 + 16 * q);
            CP16(st + ST_B1 + so, B1 + go);
            CP16(st + ST_B2 + so, B2 + go);
        }
    };

    float acc[4][4][4];
    #pragma unroll
    for (int a = 0; a < 4; a++)
        #pragma unroll
        for (int b = 0; b < 4; b++)
            #pragma unroll
            for (int c = 0; c < 4; c++) acc[a][b][c] = 0.f;

    load_stage(0, 0); CP_COMMIT();
    load_stage(1, 1); CP_COMMIT();

    for (int c = 0; c < NC; c++) {
        CP_WAIT1();
        __syncthreads();
        if (c + 2 < NC) load_stage((c + 2) % 3, c + 2);
        CP_COMMIT();

        uint32_t st = sbase + (c % 3) * ST_SZ;
        #pragma unroll
        for (int s = 0; s < 2; s++) {
            uint32_t a1[4][4], a2[4][4];
            #pragma unroll
            for (int mi = 0; mi < 4; mi++) {
                uint32_t ao = st + ((s * 8 + wm * 4 + mi) * 32 + lane) * 16;
                LDS128(a1[mi], ao);
                LDS128(a2[mi], ao + ST_A2);
            }
            uint32_t b1[8], b2[8];
            #pragma unroll
            for (int p = 0; p < 2; p++) {
                uint32_t bo = st + ST_B1 + (s * 32 + lane) * 144 + (wn * 4 + 2 * p) * 8;
                LDS128(&b1[4 * p], bo);
                LDS128(&b2[4 * p], bo + (ST_B2 - ST_B1));
            }
            #pragma unroll
            for (int mi = 0; mi < 4; mi++)
                #pragma unroll
                for (int ni = 0; ni < 4; ni++)
                    mma_bf16(acc[mi][ni], a1[mi], &b1[2 * ni]);
            #pragma unroll
            for (int mi = 0; mi < 4; mi++)
                #pragma unroll
                for (int ni = 0; ni < 4; ni++)
                    mma_bf16(acc[mi][ni], a1[mi], &b2[2 * ni]);
            #pragma unroll
            for (int mi = 0; mi < 4; mi++)
                #pragma unroll
                for (int ni = 0; ni < 4; ni++)
                    mma_bf16(acc[mi][ni], a2[mi], &b1[2 * ni]);
        }
    }
    CP_WAIT0();
    __syncthreads();

    float2 bia[4];
    #pragma unroll
    for (int ni = 0; ni < 4; ni++) {
        int col = xt * 128 + wn * 32 + ni * 8 + 2 * (lane & 3);
        bia[ni] = *(const float2*)(bias + col);
    }

    if (PHASE == 1) {
        float2 cc[4];
        #pragma unroll
        for (int ni = 0; ni < 4; ni++) {
            int col = xt * 128 + wn * 32 + ni * 8 + 2 * (lane & 3);
            cc[ni] = *(const float2*)(g_c + col);
        }
        float* S   = (float*)smem;                 // [n][m] stride 132
        float* TRB = (float*)(smem + 67584);       // [4 wn][128 rows]
        const int rb = MF + yt * 128;
        float tr[8] = {0, 0, 0, 0, 0, 0, 0, 0};
        #pragma unroll
        for (int mi = 0; mi < 4; mi++)
            #pragma unroll
            for (int ni = 0; ni < 4; ni++)
                #pragma unroll
                for (int h2 = 0; h2 < 2; h2++) {
                    int mloc = wm * 64 + mi * 16 + (lane >> 2) + 8 * h2;
                    int nb = wn * 32 + ni * 8 + 2 * (lane & 3);
                    float v0 = acc[mi][ni][2 * h2 + 0] + bia[ni].x;
                    float v1 = acc[mi][ni][2 * h2 + 1] + bia[ni].y;
                    bool m0k = (fabsf(v0) > TAU) ? (v0 > 0.f)
                        : exact_mask(zP, W1P, rb + mloc, xt * 128 + nb);
                    bool m1k = (fabsf(v1) > TAU) ? (v1 > 0.f)
                        : exact_mask(zP, W1P, rb + mloc, xt * 128 + nb + 1);
                    if (m0k) tr[mi * 2 + h2] += cc[ni].x;
                    if (m1k) tr[mi * 2 + h2] += cc[ni].y;
                    S[nb * 132 + mloc]       = fmaxf(v0, 0.f);
                    S[(nb + 1) * 132 + mloc] = fmaxf(v1, 0.f);
                }
        #pragma unroll
        for (int r = 0; r < 8; r++) {
            tr[r] += __shfl_xor_sync(0xffffffffu, tr[r], 1);
            tr[r] += __shfl_xor_sync(0xffffffffu, tr[r], 2);
        }
        if ((lane & 3) == 0) {
            #pragma unroll
            for (int r = 0; r < 8; r++) {
                int row = wm * 64 + (r >> 1) * 16 + (r & 1) * 8 + (lane >> 2);
                TRB[wn * 128 + row] = tr[r];
            }
        }
        __syncthreads();
        // h -> bf16 A-frag planes for phase 2 (8192 words)
        #pragma unroll
        for (int i = 0; i < 32; i++) {
            int idx = tid + i * 256;
            int fl = idx >> 10, sl = (idx >> 7) & 7, tt = (idx >> 2) & 31, jr = idx & 3;
            int mloc = fl * 16 + (tt >> 2) + 8 * (jr & 1);
            int qloc = sl * 8 + (tt & 3) + 4 * (jr >> 1);
            float v0 = S[(2 * qloc) * 132 + mloc];
            float v1 = S[(2 * qloc + 1) * 132 + mloc];
            uint32_t w1, w2;
            split2(v0, v1, w1, w2);
            size_t go = (((size_t)(f0 + fl) * (K2 / 16) + xt * 8 + sl) * 32 + tt) * 4 + jr;
            g_hf1[go] = w1;
            g_hf2[go] = w2;
        }
        if (tid < 128) {
            float s4 = TRB[tid] + TRB[128 + tid] + TRB[256 + tid] + TRB[384 + tid];
            g_trp[xt][rb + tid] = s4;
        }
    } else {
        #pragma unroll
        for (int mi = 0; mi < 4; mi++)
            #pragma unroll
            for (int ni = 0; ni < 4; ni++)
                #pragma unroll
                for (int h2 = 0; h2 < 2; h2++) {
                    int m = MF + yt * 128 + wm * 64 + mi * 16 + (lane >> 2) + 8 * h2;
                    int n = xt * 128 + wn * 32 + ni * 8 + 2 * (lane & 3);
                    float2 o;
                    o.x = acc[mi][ni][2 * h2 + 0] + bia[ni].x;
                    o.y = acc[mi][ni][2 * h2 + 1] + bia[ni].y;
                    *(float2*)(outp + (size_t)m * N2 + n) = o;
                }
    }
}

// ---------------- hybrid: CTA-level roles + atomic tile queues --------------
template<int PHASE>
__global__ void __launch_bounds__(256, 2)
hybrid(float* __restrict__ outp, const float* __restrict__ zP,
       const float* __restrict__ W1P) {
    constexpr int NXF = (PHASE == 1) ? (N1 / 128) : (N2 / 128);
    constexpr int NTF = (MF / 128) * NXF;
    constexpr int NXM = (PHASE == 1) ? (N1 / 128) : (N2 / 128);
    constexpr int NTM = (MR / 128) * NXM;

    extern __shared__ char smem[];
    __shared__ int s_tile;
    const int tid = threadIdx.x;
    const bool is_ffma = (blockIdx.x < NFFMA);

    for (;;) {
        if (tid == 0)
            s_tile = atomicAdd(is_ffma ? &g_qf : &g_qm, 1);
        __syncthreads();
        int t = s_tile;
        __syncthreads();
        if (is_ffma) {
            if (t >= NTF) break;
            ffma_tile<PHASE>(smem, outp, zP, t % NXF, t / NXF, tid);
        } else {
            if (t >= NTM) break;
            mma_tile<PHASE>(smem, outp, zP, W1P, t % NXM, t / NXM, tid);
        }
        __syncthreads();
    }
}

// ---------------------------------------------------------------------------
extern "C" void kernel_launch(void* const* d_in, const int* in_sizes, int n_in,
                              void* d_out, int out_size) {
    const float* t  = (const float*)d_in[0];
    const float* z  = (const float*)d_in[1];
    const float* W1 = (const float*)d_in[3];
    const float* b1 = (const float*)d_in[4];
    const float* W2 = (const float*)d_in[5];
    const float* b2 = (const float*)d_in[6];
    float* out = (float*)d_out;     // dz (NB*512) then dlogp (NB)

    cudaFuncSetAttribute(hybrid<1>, cudaFuncAttributeMaxDynamicSharedMemorySize, SMEM_BYTES);
    cudaFuncSetAttribute(hybrid<2>, cudaFuncAttributeMaxDynamicSharedMemorySize, SMEM_BYTES);

    prep_pack<<<(N1 * K1 + N2 * K2 + 255) / 256, 256>>>(W1, W2);
    prep_w<<<(N1 * K1 / 2 + N2 * K2 / 2 + 255) / 256, 256>>>(W1, W2);
    prep_zf<<<(MR * K1 / 4) / 256, 256>>>(z);
    prep_cbias<<<8, 128>>>(t, W1, b1, W2, b2);

    zero_q<<<1, 1>>>();
    hybrid<1><<<NCTA, 256, SMEM_BYTES>>>(nullptr, z, W1);
    zero_q<<<1, 1>>>();
    hybrid<2><<<NCTA, 256, SMEM_BYTES>>>(out, z, W1);

    trace_combine<<<MR / 256, 256>>>(out);
}

// round 10
// speedup vs baseline: 2.3044x; 2.3044x over previous
#include <cuda_runtime.h>

#define NB 16384
#define N1 1024
#define K1 512
#define N2 512
#define K2 1024
#define NROWB 128            // 128-row blocks
#define NT1 1024             // gemm1 tiles: 128 rowblocks x 8 ntiles
#define NT2 512              // gemm2 tiles: 128 rowblocks x 4 ntiles
#define NTILES (NT1 + NT2)
#define NCTA 304

// ---------------- device-global scratch (no allocations) -------------------
__device__ float g_W1p[N1 * K1];
__device__ float g_W2p[N2 * K2];
__device__ float g_h[(size_t)NB * N1];
__device__ float g_beff1[N1], g_beff2[N2], g_c[N1];
__device__ float g_cpart[8][N1];
__device__ int   g_q;
__device__ int   g_ready[NROWB];

// ---------------- prep A: weight repack + c partials (one launch) ----------
__global__ void prepA(const float* __restrict__ W1, const float* __restrict__ W2) {
    int bx = blockIdx.x;
    if (bx < 4096) {                         // dense repack
        int idx = bx * 256 + threadIdx.x;
        if (idx < N1 * K1) {
            int n = idx >> 9, k = idx & 511;
            g_W1p[idx] = W1[n * 513 + k];
        } else {
            int j = idx - N1 * K1;           // < N2*K2
            int n = j >> 10, k = j & 1023;
            g_W2p[j] = W2[n * 1025 + k];
        }
    } else {                                 // c partials: 32 blocks
        int b  = bx - 4096;                  // 0..31
        int jb = b >> 3;                     // j block 0..3
        int kc = b & 7;                      // k chunk 0..7 (64 k each)
        int j  = jb * 256 + threadIdx.x;
        const float* w1r = W1 + (size_t)j * 513 + kc * 64;
        float s = 0.f;
        #pragma unroll 8
        for (int k = 0; k < 64; k++)
            s += W2[(size_t)(kc * 64 + k) * 1025 + j] * w1r[k];
        g_cpart[kc][j] = s;
    }
}

// ---------------- prep B: finalize c + biases, reset queue -----------------
__global__ void prepB(const float* __restrict__ t,
                      const float* __restrict__ W1, const float* __restrict__ b1,
                      const float* __restrict__ W2, const float* __restrict__ b2) {
    int j = blockIdx.x * 256 + threadIdx.x;  // grid 4 x 256 -> j < 1024
    float t0 = t[0];
    float s = 0.f;
    #pragma unroll
    for (int k = 0; k < 8; k++) s += g_cpart[k][j];
    g_c[j] = s;
    g_beff1[j] = b1[j] + t0 * W1[(size_t)j * 513 + 512];
    if (j < N2) g_beff2[j] = b2[j] + t0 * W2[(size_t)j * 1025 + 1024];
    if (j < NROWB) g_ready[j] = 0;
    if (j == N1 - 1) g_q = 0;
}

// ---------------- unified FFMA tile (R1 body, runtime-parameterized) -------
// C[128,128] tile of A@B^T + bias; optional relu; optional trace (mask@c).
__device__ __forceinline__ void gemm_tile(
    float* As, float* Bs,
    const float* __restrict__ A, const float* __restrict__ Bw,
    float* __restrict__ outp, const float* __restrict__ bias,
    int K, int LDC, int m0, int n0,
    bool do_relu, bool do_trace, float* __restrict__ trace_out, int tid)
{
    const int lrow = tid >> 1;
    const int lk4  = (tid & 1) << 2;
    const float* Ap = A  + (size_t)(m0 + lrow) * K + lk4;
    const float* Bp = Bw + (size_t)(n0 + lrow) * K + lk4;
    const int tx = tid & 15;
    const int ty = tid >> 4;

    float acc[8][8];
    #pragma unroll
    for (int i = 0; i < 8; i++)
        #pragma unroll
        for (int j = 0; j < 8; j++) acc[i][j] = 0.f;

    float tr = 0.f;
    float4 av = *(const float4*)Ap;
    float4 bv = *(const float4*)Bp;

    for (int k0 = 0; k0 < K; k0 += 8) {
        As[(lk4 + 0) * 128 + lrow] = av.x;
        As[(lk4 + 1) * 128 + lrow] = av.y;
        As[(lk4 + 2) * 128 + lrow] = av.z;
        As[(lk4 + 3) * 128 + lrow] = av.w;
        Bs[(lk4 + 0) * 128 + lrow] = bv.x;
        Bs[(lk4 + 1) * 128 + lrow] = bv.y;
        Bs[(lk4 + 2) * 128 + lrow] = bv.z;
        Bs[(lk4 + 3) * 128 + lrow] = bv.w;

        if (do_trace) {
            const float4 cv = *(const float4*)(g_c + k0 + lk4);
            tr += (av.x > 0.f) ? cv.x : 0.f;
            tr += (av.y > 0.f) ? cv.y : 0.f;
            tr += (av.z > 0.f) ? cv.z : 0.f;
            tr += (av.w > 0.f) ? cv.w : 0.f;
        }
        __syncthreads();
        if (k0 + 8 < K) {
            av = *(const float4*)(Ap + k0 + 8);
            bv = *(const float4*)(Bp + k0 + 8);
        }
        #pragma unroll
        for (int kk = 0; kk < 8; kk++) {
            float4 a0 = *(const float4*)&As[kk * 128 + ty * 4];
            float4 a1 = *(const float4*)&As[kk * 128 + ty * 4 + 64];
            float4 b0 = *(const float4*)&Bs[kk * 128 + tx * 4];
            float4 b1 = *(const float4*)&Bs[kk * 128 + tx * 4 + 64];
            float a[8] = {a0.x, a0.y, a0.z, a0.w, a1.x, a1.y, a1.z, a1.w};
            float b[8] = {b0.x, b0.y, b0.z, b0.w, b1.x, b1.y, b1.z, b1.w};
            #pragma unroll
            for (int i = 0; i < 8; i++)
                #pragma unroll
                for (int j = 0; j < 8; j++)
                    acc[i][j] += a[i] * b[j];
        }
        __syncthreads();
    }

    const float4 be0 = *(const float4*)(bias + n0 + tx * 4);
    const float4 be1 = *(const float4*)(bias + n0 + 64 + tx * 4);
    #pragma unroll
    for (int i = 0; i < 8; i++) {
        int m = m0 + ty * 4 + (i & 3) + ((i >= 4) ? 64 : 0);
        float v[8];
        v[0] = acc[i][0] + be0.x; v[1] = acc[i][1] + be0.y;
        v[2] = acc[i][2] + be0.z; v[3] = acc[i][3] + be0.w;
        v[4] = acc[i][4] + be1.x; v[5] = acc[i][5] + be1.y;
        v[6] = acc[i][6] + be1.z; v[7] = acc[i][7] + be1.w;
        if (do_relu) {
            #pragma unroll
            for (int j = 0; j < 8; j++) v[j] = fmaxf(v[j], 0.f);
        }
        float* cp = outp + (size_t)m * LDC + n0 + tx * 4;
        *(float4*)cp        = make_float4(v[0], v[1], v[2], v[3]);
        *(float4*)(cp + 64) = make_float4(v[4], v[5], v[6], v[7]);
    }
    if (do_trace) {
        // row trace split over the 2 loader threads of each row -> fixed shfl
        float tro = __shfl_xor_sync(0xffffffffu, tr, 1);
        if ((tid & 1) == 0)
            trace_out[m0 + lrow] = -(tr + tro);
    }
}

// ---------------- persistent fused kernel: queue over both GEMMs -----------
// tiles [0, NT1): GEMM1  h = relu(z @ W1p^T + beff1)   (m-major -> early rows)
// tiles [NT1, NTILES): GEMM2  dz = h @ W2p^T + beff2 (+trace), gated on
// per-rowblock ready counters (threadfence release / acquire).
__global__ void __launch_bounds__(256, 2)
fused(const float* __restrict__ z, float* __restrict__ out) {
    __shared__ float As[8 * 128];
    __shared__ float Bs[8 * 128];
    __shared__ int s_t;
    const int tid = threadIdx.x;

    for (;;) {
        __syncthreads();
        if (tid == 0) s_t = atomicAdd(&g_q, 1);
        __syncthreads();
        const int t = s_t;
        if (t >= NTILES) return;

        if (t < NT1) {
            const int yt = t >> 3, xt = t & 7;
            gemm_tile(As, Bs, z, g_W1p, g_h, g_beff1,
                      K1, N1, yt * 128, xt * 128,
                      true, false, nullptr, tid);
            __threadfence();                 // release h stores
            __syncthreads();
            if (tid == 0) atomicAdd(&g_ready[yt], 1);
        } else {
            const int u = t - NT1;
            const int yt = u >> 2, xt = u & 3;
            if (tid == 0) {
                while (*(volatile int*)&g_ready[yt] < 8) __nanosleep(40);
            }
            __syncthreads();
            __threadfence();                 // acquire
            gemm_tile(As, Bs, g_h, g_W2p, out, g_beff2,
                      K2, N2, yt * 128, xt * 128,
                      false, xt == 0, out + (size_t)NB * N2, tid);
        }
    }
}

// ---------------------------------------------------------------------------
extern "C" void kernel_launch(void* const* d_in, const int* in_sizes, int n_in,
                              void* d_out, int out_size) {
    const float* t  = (const float*)d_in[0];
    const float* z  = (const float*)d_in[1];
    // d_in[2] = logp_z (zeros; unused)
    const float* W1 = (const float*)d_in[3];
    const float* b1 = (const float*)d_in[4];
    const float* W2 = (const float*)d_in[5];
    const float* b2 = (const float*)d_in[6];
    float* out = (float*)d_out;   // dz (NB*512) then dlogp (NB)

    prepA<<<4096 + 32, 256>>>(W1, W2);
    prepB<<<4, 256>>>(t, W1, b1, W2, b2);
    fused<<<NCTA, 256>>>(z, out);
}